// round 2
// baseline (speedup 1.0000x reference)
#include <cuda_runtime.h>
#include <math_constants.h>

#define B_ 64
#define S_ 2048
#define D_ 512
#define K2D 1024          // 2*D
#define SPLITS 16
#define ROWS_PER_SPLIT (S_ / SPLITS)   // 128
#define NW 8              // warps per block in k2

// -------- scratch (no allocations allowed) --------
__device__ float g_w[B_ * D_];                       // folded (cq_i + b_d) * W_1d
__device__ float g_pm[B_ * SPLITS];                  // per-split running max
__device__ float g_pl[B_ * SPLITS];                  // per-split denominator
__device__ float g_pacc[(size_t)B_ * SPLITS * D_];   // per-split weighted sums

// ============================================================
// k1: w[b,d] = (sum_k conc[b,k] * W_d2d[d,k] + b_d[d]) * W_1d[d]
// conc = [c_i_1 | q], K = 1024. Tile: M=64 (all b), N=64, K-tile=32.
// Grid = D/64 = 8 blocks, 256 threads (16x16), 4x4 micro-tile each.
// ============================================================
__global__ void __launch_bounds__(256) k1_gemm(
    const float* __restrict__ c_i_1, const float* __restrict__ q,
    const float* __restrict__ W, const float* __restrict__ b_d,
    const float* __restrict__ W1d)
{
    __shared__ float sA[32][65];  // [kk][b]
    __shared__ float sB[32][65];  // [kk][dd]
    const int tid = threadIdx.x;
    const int d0 = blockIdx.x * 64;
    const int tx = tid & 15, ty = tid >> 4;

    float acc[4][4];
#pragma unroll
    for (int j = 0; j < 4; j++)
#pragma unroll
        for (int i = 0; i < 4; i++) acc[j][i] = 0.f;

    for (int k0 = 0; k0 < K2D; k0 += 32) {
#pragma unroll
        for (int j = 0; j < 8; j++) {
            int i = tid + j * 256;
            int kk = i & 31, bb = i >> 5;
            int k = k0 + kk;
            sA[kk][bb] = (k < D_) ? c_i_1[bb * D_ + k] : q[bb * D_ + (k - D_)];
        }
#pragma unroll
        for (int j = 0; j < 8; j++) {
            int i = tid + j * 256;
            int kk = i & 31, dd = i >> 5;
            sB[kk][dd] = W[(size_t)(d0 + dd) * K2D + k0 + kk];
        }
        __syncthreads();
#pragma unroll
        for (int kk = 0; kk < 32; kk++) {
            float a[4], bv[4];
#pragma unroll
            for (int j = 0; j < 4; j++) a[j] = sA[kk][ty * 4 + j];
#pragma unroll
            for (int i = 0; i < 4; i++) bv[i] = sB[kk][tx * 4 + i];
#pragma unroll
            for (int j = 0; j < 4; j++)
#pragma unroll
                for (int i = 0; i < 4; i++) acc[j][i] = fmaf(a[j], bv[i], acc[j][i]);
        }
        __syncthreads();
    }

#pragma unroll
    for (int i = 0; i < 4; i++) {
        int d = d0 + tx * 4 + i;
        float bias = b_d[d], w1 = W1d[d];
#pragma unroll
        for (int j = 0; j < 4; j++) {
            int b = ty * 4 + j;
            g_w[b * D_ + d] = (acc[j][i] + bias) * w1;
        }
    }
}

// ============================================================
// k2: flash-style online softmax + weighted sum over S.
// One block = (b, split). 8 warps, each warp handles rows strided by 8.
// Lane owns d = {k*128 + lane*4 .. +3} for k = 0..3 (float4 per k).
// cw_s read exactly ONCE. b_1 dropped (softmax-invariant).
// ============================================================
__global__ void __launch_bounds__(256) k2_flash(const float* __restrict__ cw)
{
    const int tid  = threadIdx.x;
    const int lane = tid & 31;
    const int warp = tid >> 5;
    const int b     = blockIdx.x / SPLITS;
    const int split = blockIdx.x % SPLITS;

    // folded projection vector for this batch
    float4 wv[4];
    const float4* wrow = reinterpret_cast<const float4*>(g_w + b * D_);
#pragma unroll
    for (int k = 0; k < 4; k++) wv[k] = wrow[lane + 32 * k];

    float m = -CUDART_INF_F;
    float l = 0.f;
    float4 acc[4];
#pragma unroll
    for (int k = 0; k < 4; k++) { acc[k].x = acc[k].y = acc[k].z = acc[k].w = 0.f; }

    const int sbeg = split * ROWS_PER_SPLIT + warp;
    const int send = split * ROWS_PER_SPLIT + ROWS_PER_SPLIT;
    const float4* base = reinterpret_cast<const float4*>(cw);

    for (int s = sbeg; s < send; s += NW) {
        const float4* row = base + (size_t)(b * S_ + s) * (D_ / 4);
        float4 x0 = row[lane];
        float4 x1 = row[lane + 32];
        float4 x2 = row[lane + 64];
        float4 x3 = row[lane + 96];

        float t;
        t  = x0.x * wv[0].x; t = fmaf(x0.y, wv[0].y, t);
        t = fmaf(x0.z, wv[0].z, t); t = fmaf(x0.w, wv[0].w, t);
        t = fmaf(x1.x, wv[1].x, t); t = fmaf(x1.y, wv[1].y, t);
        t = fmaf(x1.z, wv[1].z, t); t = fmaf(x1.w, wv[1].w, t);
        t = fmaf(x2.x, wv[2].x, t); t = fmaf(x2.y, wv[2].y, t);
        t = fmaf(x2.z, wv[2].z, t); t = fmaf(x2.w, wv[2].w, t);
        t = fmaf(x3.x, wv[3].x, t); t = fmaf(x3.y, wv[3].y, t);
        t = fmaf(x3.z, wv[3].z, t); t = fmaf(x3.w, wv[3].w, t);

        // warp reduce (all lanes get the logit)
        t += __shfl_xor_sync(0xffffffffu, t, 16);
        t += __shfl_xor_sync(0xffffffffu, t, 8);
        t += __shfl_xor_sync(0xffffffffu, t, 4);
        t += __shfl_xor_sync(0xffffffffu, t, 2);
        t += __shfl_xor_sync(0xffffffffu, t, 1);

        float mn = fmaxf(m, t);
        float sc = __expf(m - mn);   // first iter: exp(-inf)=0
        float p  = __expf(t - mn);
        l = l * sc + p;
        acc[0].x = fmaf(acc[0].x, sc, p * x0.x); acc[0].y = fmaf(acc[0].y, sc, p * x0.y);
        acc[0].z = fmaf(acc[0].z, sc, p * x0.z); acc[0].w = fmaf(acc[0].w, sc, p * x0.w);
        acc[1].x = fmaf(acc[1].x, sc, p * x1.x); acc[1].y = fmaf(acc[1].y, sc, p * x1.y);
        acc[1].z = fmaf(acc[1].z, sc, p * x1.z); acc[1].w = fmaf(acc[1].w, sc, p * x1.w);
        acc[2].x = fmaf(acc[2].x, sc, p * x2.x); acc[2].y = fmaf(acc[2].y, sc, p * x2.y);
        acc[2].z = fmaf(acc[2].z, sc, p * x2.z); acc[2].w = fmaf(acc[2].w, sc, p * x2.w);
        acc[3].x = fmaf(acc[3].x, sc, p * x3.x); acc[3].y = fmaf(acc[3].y, sc, p * x3.y);
        acc[3].z = fmaf(acc[3].z, sc, p * x3.z); acc[3].w = fmaf(acc[3].w, sc, p * x3.w);
        m = mn;
    }

    // ---- block-level combine of the 8 warps ----
    __shared__ float sm_m[NW], sm_l[NW];
    __shared__ float sm_acc[D_];
    __shared__ float sm_L;

    sm_acc[tid] = 0.f;
    sm_acc[tid + 256] = 0.f;
    if (tid == 0) sm_L = 0.f;
    if (lane == 0) { sm_m[warp] = m; sm_l[warp] = l; }
    __syncthreads();

    float M = sm_m[0];
#pragma unroll
    for (int w = 1; w < NW; w++) M = fmaxf(M, sm_m[w]);
    float sc = __expf(m - M);

#pragma unroll
    for (int k = 0; k < 4; k++) {
        int dbase = k * 128 + lane * 4;
        atomicAdd(&sm_acc[dbase + 0], acc[k].x * sc);
        atomicAdd(&sm_acc[dbase + 1], acc[k].y * sc);
        atomicAdd(&sm_acc[dbase + 2], acc[k].z * sc);
        atomicAdd(&sm_acc[dbase + 3], acc[k].w * sc);
    }
    if (lane == 0) atomicAdd(&sm_L, l * sc);
    __syncthreads();

    const int pidx = blockIdx.x;  // == b*SPLITS + split
    g_pacc[(size_t)pidx * D_ + tid]       = sm_acc[tid];
    g_pacc[(size_t)pidx * D_ + tid + 256] = sm_acc[tid + 256];
    if (tid == 0) { g_pm[pidx] = M; g_pl[pidx] = sm_L; }
}

// ============================================================
// k3: combine the SPLITS partials per batch. Grid = B, 128 threads.
// ============================================================
__global__ void __launch_bounds__(128) k3_combine(float* __restrict__ out)
{
    const int b = blockIdx.x, tid = threadIdx.x;

    float M = -CUDART_INF_F;
#pragma unroll
    for (int i = 0; i < SPLITS; i++) M = fmaxf(M, g_pm[b * SPLITS + i]);

    float ei[SPLITS];
    float L = 0.f;
#pragma unroll
    for (int i = 0; i < SPLITS; i++) {
        ei[i] = __expf(g_pm[b * SPLITS + i] - M);
        L = fmaf(g_pl[b * SPLITS + i], ei[i], L);
    }
    const float invL = 1.f / L;

#pragma unroll
    for (int j = 0; j < 4; j++) {
        int d = j * 128 + tid;
        float s = 0.f;
#pragma unroll
        for (int i = 0; i < SPLITS; i++)
            s = fmaf(g_pacc[(size_t)(b * SPLITS + i) * D_ + d], ei[i], s);
        out[b * D_ + d] = s * invL;
    }
}

// ============================================================
extern "C" void kernel_launch(void* const* d_in, const int* in_sizes, int n_in,
                              void* d_out, int out_size)
{
    const float* c_i_1 = (const float*)d_in[0];
    const float* q     = (const float*)d_in[1];
    const float* cw_s  = (const float*)d_in[2];
    const float* W_d2d = (const float*)d_in[3];
    const float* b_d   = (const float*)d_in[4];
    const float* W_1d  = (const float*)d_in[5];
    // d_in[6] = b_1 : softmax-invariant, dropped.
    float* out = (float*)d_out;

    k1_gemm<<<D_ / 64, 256>>>(c_i_1, q, W_d2d, b_d, W_1d);
    k2_flash<<<B_ * SPLITS, 256>>>(cw_s);
    k3_combine<<<B_, 128>>>(out);
}

// round 3
// speedup vs baseline: 2.4674x; 2.4674x over previous
#include <cuda_runtime.h>
#include <math_constants.h>

#define B_ 64
#define S_ 2048
#define D_ 512
#define K2D 1024          // 2*D
#define KSPLITS 16
#define KCHUNK (K2D / KSPLITS)         // 64
#define SPLITS 16
#define ROWS_PER_SPLIT (S_ / SPLITS)   // 128
#define NW 8              // warps per block in k2

// -------- scratch (no allocations allowed) --------
__device__ float g_part[(size_t)KSPLITS * B_ * D_];  // split-K GEMM partials
__device__ float g_w[B_ * D_];                       // folded (cq_i + b_d) * W_1d
__device__ float g_pm[B_ * SPLITS];                  // per-split running max
__device__ float g_pl[B_ * SPLITS];                  // per-split denominator
__device__ float g_pacc[(size_t)B_ * SPLITS * D_];   // per-split weighted sums

// ============================================================
// k1: split-K GEMM partials. Grid = (8 d-tiles, 16 k-splits), 256 thr.
// Each block: 64(b) x 64(d) over K-chunk of 64. Two 32-wide k-subtiles.
// ============================================================
__global__ void __launch_bounds__(256) k1_gemm(
    const float* __restrict__ c_i_1, const float* __restrict__ q,
    const float* __restrict__ W)
{
    __shared__ float sA[32][65];  // [kk][b]
    __shared__ float sB[32][65];  // [kk][dd]
    const int tid = threadIdx.x;
    const int d0 = blockIdx.x * 64;
    const int ks = blockIdx.y;
    const int kbase = ks * KCHUNK;
    const int tx = tid & 15, ty = tid >> 4;

    float acc[4][4];
#pragma unroll
    for (int j = 0; j < 4; j++)
#pragma unroll
        for (int i = 0; i < 4; i++) acc[j][i] = 0.f;

    for (int k0 = kbase; k0 < kbase + KCHUNK; k0 += 32) {
#pragma unroll
        for (int j = 0; j < 8; j++) {
            int i = tid + j * 256;
            int kk = i & 31, bb = i >> 5;
            int k = k0 + kk;
            sA[kk][bb] = (k < D_) ? c_i_1[bb * D_ + k] : q[bb * D_ + (k - D_)];
        }
#pragma unroll
        for (int j = 0; j < 8; j++) {
            int i = tid + j * 256;
            int kk = i & 31, dd = i >> 5;
            sB[kk][dd] = W[(size_t)(d0 + dd) * K2D + k0 + kk];
        }
        __syncthreads();
#pragma unroll
        for (int kk = 0; kk < 32; kk++) {
            float a[4], bv[4];
#pragma unroll
            for (int j = 0; j < 4; j++) a[j] = sA[kk][ty * 4 + j];
#pragma unroll
            for (int i = 0; i < 4; i++) bv[i] = sB[kk][tx * 4 + i];
#pragma unroll
            for (int j = 0; j < 4; j++)
#pragma unroll
                for (int i = 0; i < 4; i++) acc[j][i] = fmaf(a[j], bv[i], acc[j][i]);
        }
        __syncthreads();
    }

    float* dst = g_part + (size_t)ks * B_ * D_;
#pragma unroll
    for (int i = 0; i < 4; i++) {
        int d = d0 + tx * 4 + i;
#pragma unroll
        for (int j = 0; j < 4; j++) {
            int b = ty * 4 + j;
            dst[b * D_ + d] = acc[j][i];
        }
    }
}

// ============================================================
// k1b: fold split-K partials: g_w = (sum_ks part + b_d) * W_1d
// Grid = 128 blocks x 256 threads over 32768 elements.
// ============================================================
__global__ void __launch_bounds__(256) k1b_fold(
    const float* __restrict__ b_d, const float* __restrict__ W1d)
{
    int idx = blockIdx.x * 256 + threadIdx.x;   // b*D_+d, 0..32767
    int d = idx & (D_ - 1);
    float s = 0.f;
#pragma unroll
    for (int ks = 0; ks < KSPLITS; ks++)
        s += g_part[(size_t)ks * B_ * D_ + idx];
    g_w[idx] = (s + b_d[d]) * W1d[d];
}

// ============================================================
// k2: flash-style online softmax + weighted sum over S.
// One block = (b, split). 8 warps; each warp handles rows strided by 8,
// unrolled 2 rows per online-softmax step (halves the serial chain,
// doubles load MLP). Lane owns d = {k*128 + lane*4 .. +3}, k=0..3.
// cw_s read exactly ONCE. b_1 dropped (softmax-invariant).
// ============================================================
__global__ void __launch_bounds__(256) k2_flash(const float* __restrict__ cw)
{
    const int tid  = threadIdx.x;
    const int lane = tid & 31;
    const int warp = tid >> 5;
    const int b     = blockIdx.x / SPLITS;
    const int split = blockIdx.x % SPLITS;

    float4 wv[4];
    const float4* wrow = reinterpret_cast<const float4*>(g_w + b * D_);
#pragma unroll
    for (int k = 0; k < 4; k++) wv[k] = wrow[lane + 32 * k];

    float m = -CUDART_INF_F;
    float l = 0.f;
    float4 acc[4];
#pragma unroll
    for (int k = 0; k < 4; k++) { acc[k].x = acc[k].y = acc[k].z = acc[k].w = 0.f; }

    const int sbeg = split * ROWS_PER_SPLIT + warp;
    const float4* base = reinterpret_cast<const float4*>(cw);

    // 128 rows / 8 warps = 16 rows per warp = 8 double-row iterations
#pragma unroll 2
    for (int it = 0; it < ROWS_PER_SPLIT / (2 * NW); it++) {
        int sA = sbeg + it * 2 * NW;
        int sB = sA + NW;
        const float4* rowA = base + (size_t)(b * S_ + sA) * (D_ / 4);
        const float4* rowB = base + (size_t)(b * S_ + sB) * (D_ / 4);
        float4 x[4], y[4];
#pragma unroll
        for (int k = 0; k < 4; k++) x[k] = rowA[lane + 32 * k];
#pragma unroll
        for (int k = 0; k < 4; k++) y[k] = rowB[lane + 32 * k];

        float t0 = 0.f, t1 = 0.f;
#pragma unroll
        for (int k = 0; k < 4; k++) {
            t0 = fmaf(x[k].x, wv[k].x, t0); t0 = fmaf(x[k].y, wv[k].y, t0);
            t0 = fmaf(x[k].z, wv[k].z, t0); t0 = fmaf(x[k].w, wv[k].w, t0);
            t1 = fmaf(y[k].x, wv[k].x, t1); t1 = fmaf(y[k].y, wv[k].y, t1);
            t1 = fmaf(y[k].z, wv[k].z, t1); t1 = fmaf(y[k].w, wv[k].w, t1);
        }
#pragma unroll
        for (int off = 16; off > 0; off >>= 1) {
            t0 += __shfl_xor_sync(0xffffffffu, t0, off);
            t1 += __shfl_xor_sync(0xffffffffu, t1, off);
        }

        float mn = fmaxf(m, fmaxf(t0, t1));
        float sc = __expf(m - mn);    // first iter: exp(-inf)=0
        float p0 = __expf(t0 - mn);
        float p1 = __expf(t1 - mn);
        l = fmaf(l, sc, p0 + p1);
#pragma unroll
        for (int k = 0; k < 4; k++) {
            acc[k].x = fmaf(acc[k].x, sc, fmaf(p0, x[k].x, p1 * y[k].x));
            acc[k].y = fmaf(acc[k].y, sc, fmaf(p0, x[k].y, p1 * y[k].y));
            acc[k].z = fmaf(acc[k].z, sc, fmaf(p0, x[k].z, p1 * y[k].z));
            acc[k].w = fmaf(acc[k].w, sc, fmaf(p0, x[k].w, p1 * y[k].w));
        }
        m = mn;
    }

    // ---- block-level combine of the 8 warps ----
    __shared__ float sm_m[NW], sm_l[NW];
    __shared__ float sm_acc[D_];
    __shared__ float sm_L;

    sm_acc[tid] = 0.f;
    sm_acc[tid + 256] = 0.f;
    if (tid == 0) sm_L = 0.f;
    if (lane == 0) { sm_m[warp] = m; sm_l[warp] = l; }
    __syncthreads();

    float M = sm_m[0];
#pragma unroll
    for (int w = 1; w < NW; w++) M = fmaxf(M, sm_m[w]);
    float sc = __expf(m - M);

#pragma unroll
    for (int k = 0; k < 4; k++) {
        int dbase = k * 128 + lane * 4;
        atomicAdd(&sm_acc[dbase + 0], acc[k].x * sc);
        atomicAdd(&sm_acc[dbase + 1], acc[k].y * sc);
        atomicAdd(&sm_acc[dbase + 2], acc[k].z * sc);
        atomicAdd(&sm_acc[dbase + 3], acc[k].w * sc);
    }
    if (lane == 0) atomicAdd(&sm_L, l * sc);
    __syncthreads();

    const int pidx = blockIdx.x;  // == b*SPLITS + split
    g_pacc[(size_t)pidx * D_ + tid]       = sm_acc[tid];
    g_pacc[(size_t)pidx * D_ + tid + 256] = sm_acc[tid + 256];
    if (tid == 0) { g_pm[pidx] = M; g_pl[pidx] = sm_L; }
}

// ============================================================
// k3: combine the SPLITS partials per batch. Grid = B, 128 threads.
// ============================================================
__global__ void __launch_bounds__(128) k3_combine(float* __restrict__ out)
{
    const int b = blockIdx.x, tid = threadIdx.x;

    float M = -CUDART_INF_F;
#pragma unroll
    for (int i = 0; i < SPLITS; i++) M = fmaxf(M, g_pm[b * SPLITS + i]);

    float ei[SPLITS];
    float L = 0.f;
#pragma unroll
    for (int i = 0; i < SPLITS; i++) {
        ei[i] = __expf(g_pm[b * SPLITS + i] - M);
        L = fmaf(g_pl[b * SPLITS + i], ei[i], L);
    }
    const float invL = 1.f / L;

#pragma unroll
    for (int j = 0; j < 4; j++) {
        int d = j * 128 + tid;
        float s = 0.f;
#pragma unroll
        for (int i = 0; i < SPLITS; i++)
            s = fmaf(g_pacc[(size_t)(b * SPLITS + i) * D_ + d], ei[i], s);
        out[b * D_ + d] = s * invL;
    }
}

// ============================================================
extern "C" void kernel_launch(void* const* d_in, const int* in_sizes, int n_in,
                              void* d_out, int out_size)
{
    const float* c_i_1 = (const float*)d_in[0];
    const float* q     = (const float*)d_in[1];
    const float* cw_s  = (const float*)d_in[2];
    const float* W_d2d = (const float*)d_in[3];
    const float* b_d   = (const float*)d_in[4];
    const float* W_1d  = (const float*)d_in[5];
    // d_in[6] = b_1 : softmax-invariant, dropped.
    float* out = (float*)d_out;

    dim3 g1(D_ / 64, KSPLITS);
    k1_gemm<<<g1, 256>>>(c_i_1, q, W_d2d);
    k1b_fold<<<(B_ * D_) / 256, 256>>>(b_d, W_1d);
    k2_flash<<<B_ * SPLITS, 256>>>(cw_s);
    k3_combine<<<B_, 128>>>(out);
}